// round 3
// baseline (speedup 1.0000x reference)
#include <cuda_runtime.h>

#define NROW 1024
#define HDIM 300
#define MID  100
#define NJ   1025
#define OUT_LD 1025
#define MPAD 104
#define S2P  1088
#define SCP  1088
#define GRID 136
#define S2TP 36          // s2 tile pitch in u64 pairs

// ---- device scratch (zero-initialized at load; pads never written -> stay 0) ----
__device__ __align__(16) float g_s1[NROW * MPAD];
__device__ __align__(16) float g_s2T[MID * S2P];
__device__ __align__(16) float2 g_w2d[MID];
__device__ __align__(16) float g_scores[NROW * SCP];   // exp(score) scratch
__device__ float g_C[1];
__device__ float g_blockloss[GRID];
__device__ volatile unsigned g_barA, g_barB, g_barC;

__device__ __forceinline__ void pair_step(unsigned long long& acc, unsigned long long a2,
                                          unsigned long long p, unsigned long long w2) {
    asm volatile(
        "{\n\t"
        ".reg .b32 lo, hi, f0, f1, h2, t2;\n\t"
        ".reg .b16 q0, q1;\n\t"
        ".reg .b64 s, tf;\n\t"
        "add.rn.f32x2 s, %1, %2;\n\t"
        "mov.b64 {lo, hi}, s;\n\t"
        "cvt.rn.f16x2.f32 h2, hi, lo;\n\t"
        "tanh.approx.f16x2 t2, h2;\n\t"
        "mov.b32 {q0, q1}, t2;\n\t"
        "cvt.f32.f16 f0, q0;\n\t"
        "cvt.f32.f16 f1, q1;\n\t"
        "mov.b64 tf, {f0, f1};\n\t"
        "fma.rn.f32x2 %0, %3, tf, %0;\n\t"
        "}"
        : "+l"(acc)
        : "l"(a2), "l"(p), "l"(w2));
}

__device__ __forceinline__ void gbar(volatile unsigned* c) {
    __syncthreads();
    if (threadIdx.x == 0) {
        __threadfence();
        atomicAdd((unsigned*)c, 1u);
        while (*c < GRID) { }
        __threadfence();
    }
    __syncthreads();
}

__global__ void __launch_bounds__(256) fused_all(const float* __restrict__ sent,
                                                 const float* __restrict__ W1,
                                                 const float* __restrict__ b1,
                                                 const float* __restrict__ W2,
                                                 const float* __restrict__ b2,
                                                 const int* __restrict__ tgt,
                                                 float* __restrict__ out) {
    __shared__ __align__(16) char sm[43520];
    int bid = blockIdx.x;
    int tid = threadIdx.x;

    // ================= Phase A: dual GEMM (blocks 0..127) + prep (block 135) =================
    if (bid < 128) {
        float4* rs4 = (float4*)sm;                 // [16][16] (15 used per row)
        float4* ws4 = (float4*)(sm + 4096);        // [112][16]
        bool isS1 = (bid < 64);
        int r0 = (bid & 63) * 16;
        int woff = isS1 ? 0 : HDIM;
        const float* src = sent + (size_t)r0 * HDIM;

        int r  = tid & 15;
        int mg = tid >> 4;
        int m0 = mg * 7;

        float acc[7];
#pragma unroll
        for (int c = 0; c < 7; c++) acc[c] = 0.f;

        for (int hc = 0; hc < HDIM; hc += 60) {
            for (int q = tid; q < 16 * 15; q += 256) {
                int rr = q / 15, h4 = q % 15;
                rs4[rr * 16 + h4] = *(const float4*)(src + rr * HDIM + hc + h4 * 4);
            }
            for (int q = tid; q < 112 * 15; q += 256) {
                int m = q / 15, h4 = q % 15;
                float4 v = make_float4(0.f, 0.f, 0.f, 0.f);
                if (m < MID) v = *(const float4*)(W1 + m * (2 * HDIM) + woff + hc + h4 * 4);
                ws4[m * 16 + h4] = v;
            }
            __syncthreads();
#pragma unroll
            for (int h4 = 0; h4 < 15; h4++) {
                float4 rv = rs4[r * 16 + h4];
#pragma unroll
                for (int c = 0; c < 7; c++) {
                    float4 wv = ws4[(m0 + c) * 16 + h4];
                    acc[c] = fmaf(rv.x, wv.x, acc[c]);
                    acc[c] = fmaf(rv.y, wv.y, acc[c]);
                    acc[c] = fmaf(rv.z, wv.z, acc[c]);
                    acc[c] = fmaf(rv.w, wv.w, acc[c]);
                }
            }
            __syncthreads();
        }

        if (isS1) {
            int i = r0 + r;
#pragma unroll
            for (int c = 0; c < 7; c++) {
                int m = m0 + c;
                if (m < MID) g_s1[i * MPAD + m] = 0.5f * acc[c];
            }
        } else {
            int j = r0 + r + 1;
#pragma unroll
            for (int c = 0; c < 7; c++) {
                int m = m0 + c;
                if (m < MID) g_s2T[m * S2P + j] = 0.5f * (acc[c] + b1[m]);
            }
        }
    } else if (bid == 135) {
        if (tid < MID) {
            float w = W2[tid];
            g_w2d[tid] = make_float2(0.5f * w, 0.5f * w);
            g_s2T[tid * S2P + 0] = 0.5f * b1[tid];
        }
        if (tid == 0) {
            float s = 0.f;
#pragma unroll
            for (int m = 0; m < MID; m++) s += W2[m];
            g_C[0] = b2[0] + 0.5f * s;
        }
    }

    gbar(&g_barA);

    // ================= Phase B: scores -> exp, loss partials (4 tiles per block) =================
    {
        float* s1t = (float*)sm;                                   // [32][104]
        unsigned long long* s2t = (unsigned long long*)(sm + 13312); // [100][36]
        unsigned long long* w2t = (unsigned long long*)(sm + 42112); // [100]

        if (tid < MID) {
            float2 w = g_w2d[tid];
            w2t[tid] = *(unsigned long long*)&w;
        }
        float C = g_C[0];
        float lossacc = 0.f;

        int ti = tid >> 3;
        int tg = tid & 7;

        for (int t = 0; t < 4; t++) {
            int tile = t * GRID + bid;          // 0..543
            int jb = tile % 17, ib = tile / 17;
            int i0 = ib * 32, j0 = jb * 64;

            for (int q = tid; q < 32 * MPAD; q += 256)
                s1t[q] = g_s1[(i0 + q / MPAD) * MPAD + (q % MPAD)];
            for (int q = tid; q < MID * 16; q += 256) {
                int m = q >> 4, f4 = q & 15;
                float4 v = *(const float4*)(g_s2T + m * S2P + j0 + f4 * 4);
                *((float4*)(s2t + m * S2TP) + f4) = v;
            }
            __syncthreads();

            unsigned long long acc0 = 0ull, acc1 = 0ull, acc2 = 0ull, acc3 = 0ull;
#pragma unroll 2
            for (int m = 0; m < MID; m++) {
                float a = s1t[ti * MPAD + m];
                unsigned long long a2;
                asm("mov.b64 %0, {%1, %1};" : "=l"(a2) : "f"(a));
                unsigned long long w2 = w2t[m];
                ulonglong2 p01 = *((const ulonglong2*)(s2t + m * S2TP) + 2 * tg);
                ulonglong2 p23 = *((const ulonglong2*)(s2t + m * S2TP) + 2 * tg + 1);
                pair_step(acc0, a2, p01.x, w2);
                pair_step(acc1, a2, p01.y, w2);
                pair_step(acc2, a2, p23.x, w2);
                pair_step(acc3, a2, p23.y, w2);
            }

            int i = i0 + ti;
            int jbase = j0 + tg * 8;
            int tgv = tgt[i];
            float o[8];
            asm("mov.b64 {%0,%1}, %2;" : "=f"(o[0]), "=f"(o[1]) : "l"(acc0));
            asm("mov.b64 {%0,%1}, %2;" : "=f"(o[2]), "=f"(o[3]) : "l"(acc1));
            asm("mov.b64 {%0,%1}, %2;" : "=f"(o[4]), "=f"(o[5]) : "l"(acc2));
            asm("mov.b64 {%0,%1}, %2;" : "=f"(o[6]), "=f"(o[7]) : "l"(acc3));
            float e[8];
#pragma unroll
            for (int c = 0; c < 8; c++) {
                int j = jbase + c;
                float s = o[c] + C;
                e[c] = __expf(s);
                if (j < NJ) lossacc += fabsf(s - ((j == tgv) ? 1.f : 0.f));
            }
            float* dst = g_scores + (size_t)i * SCP + jbase;
            *(float4*)dst       = make_float4(e[0], e[1], e[2], e[3]);
            *(float4*)(dst + 4) = make_float4(e[4], e[5], e[6], e[7]);
            __syncthreads();
        }

        // block-level deterministic loss reduction
#pragma unroll
        for (int off = 16; off > 0; off >>= 1)
            lossacc += __shfl_xor_sync(0xffffffffu, lossacc, off);
        float* red = (float*)sm;
        if ((tid & 31) == 0) red[tid >> 5] = lossacc;
        __syncthreads();
        if (tid == 0) {
            float s = red[0];
#pragma unroll
            for (int w = 1; w < 8; w++) s += red[w];
            g_blockloss[bid] = s;
        }
    }

    gbar(&g_barB);

    // ================= Phase C: row sums + normalize (blocks 0..127), loss (block 0) =================
    if (bid == 0 && tid == 0) {
        float s = 0.f;
        for (int b = 0; b < GRID; b++) s += g_blockloss[b];
        out[0] = s * (1.0f / (1024.0f * 1025.0f));
    }

    if (bid < 128) {
        float* red = (float*)(sm + 1024);
        for (int rr = 0; rr < 8; rr++) {
            int i = bid * 8 + rr;
            const float* row = g_scores + (size_t)i * SCP;
            float4 v = ((const float4*)row)[tid];
            float extra = row[1024];
            float sum = v.x + v.y + v.z + v.w;
            if (tid == 0) sum += extra;
#pragma unroll
            for (int off = 16; off > 0; off >>= 1)
                sum += __shfl_xor_sync(0xffffffffu, sum, off);
            if ((tid & 31) == 0) red[tid >> 5] = sum;
            __syncthreads();
            float tot = 0.f;
#pragma unroll
            for (int w = 0; w < 8; w++) tot += red[w];
            float inv = 1.0f / tot;
            float* o = out + 1 + (size_t)i * OUT_LD + 4 * tid;
            o[0] = v.x * inv;
            o[1] = v.y * inv;
            o[2] = v.z * inv;
            o[3] = v.w * inv;
            if (tid == 0) out[1 + (size_t)i * OUT_LD + 1024] = extra * inv;
            __syncthreads();
        }
    }

    // ================= replay-safe barrier reset =================
    __syncthreads();
    if (tid == 0) {
        __threadfence();
        unsigned v = atomicAdd((unsigned*)&g_barC, 1u);
        if (v == GRID - 1) {
            g_barA = 0;
            g_barB = 0;
            __threadfence();
            g_barC = 0;
        }
    }
}

extern "C" void kernel_launch(void* const* d_in, const int* in_sizes, int n_in,
                              void* d_out, int out_size) {
    const float* sentence;
    const int*   tgt;
    const float* W1;
    const float* b1;
    const float* W2;
    const float* b2;

    if (n_in >= 6 && in_sizes[1] == 1024) {
        sentence = (const float*)d_in[0];
        tgt      = (const int*)d_in[1];
        W1       = (const float*)d_in[2];
        b1       = (const float*)d_in[3];
        W2       = (const float*)d_in[4];
        b2       = (const float*)d_in[5];
    } else {
        sentence = (const float*)d_in[0];
        W1       = (const float*)d_in[1];
        b1       = (const float*)d_in[2];
        W2       = (const float*)d_in[3];
        b2       = (const float*)d_in[4];
        tgt      = (const int*)d_in[5];
    }

    float* out = (float*)d_out;
    fused_all<<<GRID, 256>>>(sentence, W1, b1, W2, b2, tgt, out);
}

// round 6
// speedup vs baseline: 1.3702x; 1.3702x over previous
#include <cuda_runtime.h>
#include <cuda_fp16.h>

#define NROW 1024
#define HDIM 300
#define MID  100
#define NJ   1025
#define OUT_LD 1025
#define MPAD 104
#define S2P  1088
#define SCP  1088
#define NTILE 544        // 17 j-tiles x 32 i-tiles
#define S2HP 72          // k2 s2 tile pitch in halves (64 + 8 pad)

// ---- device scratch (zero-initialized at load; pads never written -> stay 0) ----
__device__ __align__(16) float g_s1[NROW * MPAD];
__device__ __align__(16) float g_s2T[MID * S2P];
__device__ __align__(16) float g_w2[MID];          // 0.5*w2
__device__ __align__(16) float g_scores[NROW * SCP]; // exp(score) scratch
__device__ float g_C[1];
__device__ float g_blockloss[NTILE];
__device__ unsigned g_done;

__device__ __forceinline__ __half2 tanh_h2(__half2 x) {
    unsigned r, xi = *reinterpret_cast<unsigned*>(&x);
    asm("tanh.approx.f16x2 %0, %1;" : "=r"(r) : "r"(xi));
    return *reinterpret_cast<__half2*>(&r);
}

// ================= k1: dual GEMM (blocks 0..127) + prep (block 128) =================
#define HC 60
__global__ void __launch_bounds__(128) k1_gemm(const float* __restrict__ sent,
                                               const float* __restrict__ W1,
                                               const float* __restrict__ b1,
                                               const float* __restrict__ W2,
                                               const float* __restrict__ b2) {
    int b = blockIdx.x;
    int tid = threadIdx.x;

    if (b == 128) {   // prep
        if (tid < MID) {
            g_w2[tid] = 0.5f * W2[tid];
            g_s2T[tid * S2P + 0] = 0.5f * b1[tid];   // j=0: pm row is zeros
        }
        if (tid == 0) {
            float s = 0.f;
#pragma unroll
            for (int m = 0; m < MID; m++) s += W2[m];
            g_C[0] = b2[0] + 0.5f * s;
        }
        return;
    }

    __shared__ float4 rs4[16][16];      // rows x h4 (15 used)
    __shared__ float4 ws4[MPAD][16];    // m x h4

    bool isS1 = (b < 64);
    int r0 = (b & 63) * 16;
    int woff = isS1 ? 0 : HDIM;
    const float* src = sent + (size_t)r0 * HDIM;

    int r  = tid & 15;
    int mg = tid >> 4;
    int m0 = mg * 13;

    float acc[13];
#pragma unroll
    for (int c = 0; c < 13; c++) acc[c] = 0.f;

    for (int hc = 0; hc < HDIM; hc += HC) {
        for (int q = tid; q < 16 * 15; q += 128) {
            int rr = q / 15, h4 = q % 15;
            rs4[rr][h4] = *(const float4*)(src + rr * HDIM + hc + h4 * 4);
        }
        for (int q = tid; q < MPAD * 15; q += 128) {
            int m = q / 15, h4 = q % 15;
            float4 v = make_float4(0.f, 0.f, 0.f, 0.f);
            if (m < MID) v = *(const float4*)(W1 + m * (2 * HDIM) + woff + hc + h4 * 4);
            ws4[m][h4] = v;
        }
        __syncthreads();
#pragma unroll
        for (int h4 = 0; h4 < 15; h4++) {
            float4 rv = rs4[r][h4];
#pragma unroll
            for (int c = 0; c < 13; c++) {
                float4 wv = ws4[m0 + c][h4];
                acc[c] = fmaf(rv.x, wv.x, acc[c]);
                acc[c] = fmaf(rv.y, wv.y, acc[c]);
                acc[c] = fmaf(rv.z, wv.z, acc[c]);
                acc[c] = fmaf(rv.w, wv.w, acc[c]);
            }
        }
        __syncthreads();
    }

    if (isS1) {
        int i = r0 + r;
#pragma unroll
        for (int c = 0; c < 13; c++) {
            int m = m0 + c;
            if (m < MID) g_s1[i * MPAD + m] = 0.5f * acc[c];
        }
    } else {
        int j = r0 + r + 1;
#pragma unroll
        for (int c = 0; c < 13; c++) {
            int m = m0 + c;
            if (m < MID) g_s2T[m * S2P + j] = 0.5f * (acc[c] + b1[m]);
        }
    }
}

// ================= k2: pairwise scores (f16 add + f16x2 tanh, f32 accumulate) =================
// Tile 32i x 64j, 256 threads: thread = 1 i x 8 j. Also: exp(score) store + loss partial.
__global__ void __launch_bounds__(256) k2_scores(const int* __restrict__ tgt) {
    __shared__ float  s1t[32][MPAD];
    __shared__ __align__(16) __half s2h[MID * S2HP];   // [m][j] as f16
    __shared__ float  w2t[MID];
    __shared__ float  csh;
    __shared__ float  red[8];

    int tid = threadIdx.x;
    int i0 = blockIdx.y * 32;
    int j0 = blockIdx.x * 64;

    for (int q = tid; q < 32 * MPAD; q += 256)
        s1t[q / MPAD][q % MPAD] = g_s1[(i0 + q / MPAD) * MPAD + (q % MPAD)];
    for (int q = tid; q < MID * 16; q += 256) {
        int m = q >> 4, f4 = q & 15;
        float4 v = *(const float4*)(g_s2T + m * S2P + j0 + f4 * 4);
        __half2 h0 = __floats2half2_rn(v.x, v.y);
        __half2 h1 = __floats2half2_rn(v.z, v.w);
        *(__half2*)(s2h + m * S2HP + f4 * 4)     = h0;
        *(__half2*)(s2h + m * S2HP + f4 * 4 + 2) = h1;
    }
    if (tid < MID) w2t[tid] = g_w2[tid];
    if (tid == 0) csh = g_C[0];
    __syncthreads();

    int ti = tid >> 3;
    int tg = tid & 7;
    float acc[8];
#pragma unroll
    for (int c = 0; c < 8; c++) acc[c] = 0.f;

#pragma unroll 2
    for (int m = 0; m < MID; m++) {
        __half2 ah = __float2half2_rn(s1t[ti][m]);
        float w = w2t[m];
        uint4 pv = *(const uint4*)(s2h + m * S2HP + tg * 8);  // 8 halves
#pragma unroll
        for (int c = 0; c < 4; c++) {
            unsigned pu = (c == 0) ? pv.x : (c == 1) ? pv.y : (c == 2) ? pv.z : pv.w;
            __half2 p = *reinterpret_cast<__half2*>(&pu);
            __half2 t = tanh_h2(__hadd2(ah, p));
            acc[2 * c]     = fmaf(w, __low2float(t),  acc[2 * c]);
            acc[2 * c + 1] = fmaf(w, __high2float(t), acc[2 * c + 1]);
        }
    }

    float C = csh;
    int i = i0 + ti;
    int jbase = j0 + tg * 8;
    int tgv = tgt[i];
    float lossacc = 0.f;
    float e[8];
#pragma unroll
    for (int c = 0; c < 8; c++) {
        int j = jbase + c;
        float s = acc[c] + C;
        e[c] = __expf(s);
        if (j < NJ) lossacc += fabsf(s - ((j == tgv) ? 1.f : 0.f));
    }
    float* dst = g_scores + (size_t)i * SCP + jbase;
    *(float4*)dst       = make_float4(e[0], e[1], e[2], e[3]);
    *(float4*)(dst + 4) = make_float4(e[4], e[5], e[6], e[7]);

    // deterministic block loss reduce
#pragma unroll
    for (int off = 16; off > 0; off >>= 1)
        lossacc += __shfl_xor_sync(0xffffffffu, lossacc, off);
    if ((tid & 31) == 0) red[tid >> 5] = lossacc;
    __syncthreads();
    if (tid == 0) {
        float s = red[0];
#pragma unroll
        for (int w = 1; w < 8; w++) s += red[w];
        g_blockloss[blockIdx.y * 17 + blockIdx.x] = s;
    }
}

// ================= k3: row-sum + normalize; last block reduces loss =================
__global__ void __launch_bounds__(256) k3_softmax(float* __restrict__ out) {
    __shared__ float red[8];
    __shared__ bool amLast;
    int i = blockIdx.x, t = threadIdx.x;
    const float* row = g_scores + (size_t)i * SCP;
    float4 v = ((const float4*)row)[t];
    float extra = row[1024];
    float sum = v.x + v.y + v.z + v.w;
    if (t == 0) sum += extra;
#pragma unroll
    for (int off = 16; off > 0; off >>= 1)
        sum += __shfl_xor_sync(0xffffffffu, sum, off);
    if ((t & 31) == 0) red[t >> 5] = sum;
    __syncthreads();
    float tot = 0.f;
#pragma unroll
    for (int w = 0; w < 8; w++) tot += red[w];
    float inv = 1.0f / tot;
    float* o = out + 1 + (size_t)i * OUT_LD + 4 * t;
    o[0] = v.x * inv;
    o[1] = v.y * inv;
    o[2] = v.z * inv;
    o[3] = v.w * inv;
    if (t == 0) out[1 + (size_t)i * OUT_LD + 1024] = extra * inv;

    // ticket: last block computes the loss from k2's per-block partials
    if (t == 0) {
        __threadfence();
        amLast = (atomicAdd(&g_done, 1u) == NROW - 1);
    }
    __syncthreads();
    if (amLast) {
        float s = g_blockloss[t] + g_blockloss[t + 256];
        if (t < NTILE - 512) s += g_blockloss[t + 512];
#pragma unroll
        for (int off = 16; off > 0; off >>= 1)
            s += __shfl_xor_sync(0xffffffffu, s, off);
        if ((t & 31) == 0) red[t >> 5] = s;
        __syncthreads();
        if (t == 0) {
            float tl = 0.f;
#pragma unroll
            for (int w = 0; w < 8; w++) tl += red[w];
            out[0] = tl * (1.0f / (1024.0f * 1025.0f));
            g_done = 0;   // replay-safe reset
        }
    }
}

extern "C" void kernel_launch(void* const* d_in, const int* in_sizes, int n_in,
                              void* d_out, int out_size) {
    const float* sentence;
    const int*   tgt;
    const float* W1;
    const float* b1;
    const float* W2;
    const float* b2;

    if (n_in >= 6 && in_sizes[1] == 1024) {
        sentence = (const float*)d_in[0];
        tgt      = (const int*)d_in[1];
        W1       = (const float*)d_in[2];
        b1       = (const float*)d_in[3];
        W2       = (const float*)d_in[4];
        b2       = (const float*)d_in[5];
    } else {
        sentence = (const float*)d_in[0];
        W1       = (const float*)d_in[1];
        b1       = (const float*)d_in[2];
        W2       = (const float*)d_in[3];
        b2       = (const float*)d_in[4];
        tgt      = (const int*)d_in[5];
    }

    float* out = (float*)d_out;

    k1_gemm<<<129, 128>>>(sentence, W1, b1, W2, b2);
    dim3 g2(17, 32);
    k2_scores<<<g2, 256>>>(tgt);
    k3_softmax<<<1024, 256>>>(out);
}

// round 8
// speedup vs baseline: 1.4146x; 1.0324x over previous
#include <cuda_runtime.h>
#include <cuda_fp16.h>

#define NROW 1024
#define HDIM 300
#define MID  100
#define NJ   1025
#define OUT_LD 1025
#define MPAD 104
#define S2P  1088
#define SCP  1088
#define NTILE 544        // 17 j-tiles x 32 i-tiles
#define S2HP 72          // k2 s2 tile pitch in halves (64 + 8 pad)

// ---- device scratch (zero-initialized at load; pads never written -> stay 0) ----
__device__ __align__(16) float g_s1[NROW * MPAD];
__device__ __align__(16) float g_s2T[MID * S2P];
__device__ __align__(16) float g_w2[MID];          // 0.5*w2
__device__ __align__(16) float g_scores[NROW * SCP]; // exp(score) scratch
__device__ float g_C[1];
__device__ float g_blockloss[NTILE];
__device__ unsigned g_done;

__device__ __forceinline__ __half2 tanh_h2(__half2 x) {
    unsigned r, xi = *reinterpret_cast<unsigned*>(&x);
    asm("tanh.approx.f16x2 %0, %1;" : "=r"(r) : "r"(xi));
    return *reinterpret_cast<__half2*>(&r);
}

// ================= k1: dual GEMM (blocks 0..127) + prep (block 128) =================
// 256 threads: row = tid&15 (16 rows/block), mg = tid>>4 (16 groups x 7 m).
// Warp = 16 rows x 2 m-groups -> wv LDS is 2-address broadcast; rv is 16x16B.
#define HC 60
__global__ void __launch_bounds__(256) k1_gemm(const float* __restrict__ sent,
                                               const float* __restrict__ W1,
                                               const float* __restrict__ b1,
                                               const float* __restrict__ W2,
                                               const float* __restrict__ b2) {
    int b = blockIdx.x;
    int tid = threadIdx.x;

    if (b == 128) {   // prep
        if (tid < MID) {
            g_w2[tid] = 0.5f * W2[tid];
            g_s2T[tid * S2P + 0] = 0.5f * b1[tid];   // j=0: pm row is zeros
        }
        if (tid == 0) {
            float s = 0.f;
#pragma unroll
            for (int m = 0; m < MID; m++) s += W2[m];
            g_C[0] = b2[0] + 0.5f * s;
        }
        return;
    }

    __shared__ float4 rs4[16][17];      // 16 rows x 15 used h4 (pitch 17 kills bank conflicts)
    __shared__ float4 ws4[112][17];     // 112 m x 15 used h4

    bool isS1 = (b < 64);
    int r0 = (b & 63) * 16;
    int woff = isS1 ? 0 : HDIM;
    const float* src = sent + (size_t)r0 * HDIM;

    int r  = tid & 15;
    int mg = tid >> 4;
    int m0 = mg * 7;

    float acc[7];
#pragma unroll
    for (int c = 0; c < 7; c++) acc[c] = 0.f;

    for (int hc = 0; hc < HDIM; hc += HC) {
        // stage rows: 240 float4
        if (tid < 240) {
            int rr = tid / 15, h4 = tid % 15;
            rs4[rr][h4] = *(const float4*)(src + rr * HDIM + hc + h4 * 4);
        }
        // stage weights: 1680 float4 (m>=100 zero)
        for (int q = tid; q < 112 * 15; q += 256) {
            int m = q / 15, h4 = q % 15;
            float4 v = make_float4(0.f, 0.f, 0.f, 0.f);
            if (m < MID) v = *(const float4*)(W1 + m * (2 * HDIM) + woff + hc + h4 * 4);
            ws4[m][h4] = v;
        }
        __syncthreads();
#pragma unroll
        for (int h4 = 0; h4 < 15; h4++) {
            float4 rv = rs4[r][h4];
#pragma unroll
            for (int c = 0; c < 7; c++) {
                float4 wv = ws4[m0 + c][h4];
                acc[c] = fmaf(rv.x, wv.x, acc[c]);
                acc[c] = fmaf(rv.y, wv.y, acc[c]);
                acc[c] = fmaf(rv.z, wv.z, acc[c]);
                acc[c] = fmaf(rv.w, wv.w, acc[c]);
            }
        }
        __syncthreads();
    }

    if (isS1) {
        int i = r0 + r;
#pragma unroll
        for (int c = 0; c < 7; c++) {
            int m = m0 + c;
            if (m < MID) g_s1[i * MPAD + m] = 0.5f * acc[c];
        }
    } else {
        int j = r0 + r + 1;
#pragma unroll
        for (int c = 0; c < 7; c++) {
            int m = m0 + c;
            if (m < MID) g_s2T[m * S2P + j] = 0.5f * (acc[c] + b1[m]);
        }
    }
}

// ================= k2: pairwise scores (f16 add + f16x2 tanh, f32 accumulate) =================
// Tile 32i x 64j, 256 threads: thread = 1 i x 8 j. Also: exp(score) store + loss partial.
__global__ void __launch_bounds__(256) k2_scores(const int* __restrict__ tgt) {
    __shared__ float  s1t[32][MPAD];
    __shared__ __align__(16) __half s2h[MID * S2HP];   // [m][j] as f16
    __shared__ float  w2t[MID];
    __shared__ float  csh;
    __shared__ float  red[8];

    int tid = threadIdx.x;
    int i0 = blockIdx.y * 32;
    int j0 = blockIdx.x * 64;

    for (int q = tid; q < 32 * MPAD; q += 256)
        s1t[q / MPAD][q % MPAD] = g_s1[(i0 + q / MPAD) * MPAD + (q % MPAD)];
    for (int q = tid; q < MID * 16; q += 256) {
        int m = q >> 4, f4 = q & 15;
        float4 v = *(const float4*)(g_s2T + m * S2P + j0 + f4 * 4);
        __half2 h0 = __floats2half2_rn(v.x, v.y);
        __half2 h1 = __floats2half2_rn(v.z, v.w);
        *(__half2*)(s2h + m * S2HP + f4 * 4)     = h0;
        *(__half2*)(s2h + m * S2HP + f4 * 4 + 2) = h1;
    }
    if (tid < MID) w2t[tid] = g_w2[tid];
    if (tid == 0) csh = g_C[0];
    __syncthreads();

    int ti = tid >> 3;
    int tg = tid & 7;
    float acc[8];
#pragma unroll
    for (int c = 0; c < 8; c++) acc[c] = 0.f;

#pragma unroll 2
    for (int m = 0; m < MID; m++) {
        __half2 ah = __float2half2_rn(s1t[ti][m]);
        float w = w2t[m];
        uint4 pv = *(const uint4*)(s2h + m * S2HP + tg * 8);  // 8 halves
#pragma unroll
        for (int c = 0; c < 4; c++) {
            unsigned pu = (c == 0) ? pv.x : (c == 1) ? pv.y : (c == 2) ? pv.z : pv.w;
            __half2 p = *reinterpret_cast<__half2*>(&pu);
            __half2 t = tanh_h2(__hadd2(ah, p));
            acc[2 * c]     = fmaf(w, __low2float(t),  acc[2 * c]);
            acc[2 * c + 1] = fmaf(w, __high2float(t), acc[2 * c + 1]);
        }
    }

    float C = csh;
    int i = i0 + ti;
    int jbase = j0 + tg * 8;
    int tgv = tgt[i];
    float lossacc = 0.f;
    float e[8];
#pragma unroll
    for (int c = 0; c < 8; c++) {
        int j = jbase + c;
        float s = acc[c] + C;
        e[c] = __expf(s);
        if (j < NJ) lossacc += fabsf(s - ((j == tgv) ? 1.f : 0.f));
    }
    float* dst = g_scores + (size_t)i * SCP + jbase;
    *(float4*)dst       = make_float4(e[0], e[1], e[2], e[3]);
    *(float4*)(dst + 4) = make_float4(e[4], e[5], e[6], e[7]);

    // deterministic block loss reduce
#pragma unroll
    for (int off = 16; off > 0; off >>= 1)
        lossacc += __shfl_xor_sync(0xffffffffu, lossacc, off);
    if ((tid & 31) == 0) red[tid >> 5] = lossacc;
    __syncthreads();
    if (tid == 0) {
        float s = red[0];
#pragma unroll
        for (int w = 1; w < 8; w++) s += red[w];
        g_blockloss[blockIdx.y * 17 + blockIdx.x] = s;
    }
}

// ================= k3: row-sum + normalize; last block reduces loss =================
__global__ void __launch_bounds__(256) k3_softmax(float* __restrict__ out) {
    __shared__ float red[8];
    __shared__ bool amLast;
    int i = blockIdx.x, t = threadIdx.x;
    const float* row = g_scores + (size_t)i * SCP;
    float4 v = ((const float4*)row)[t];
    float extra = row[1024];
    float sum = v.x + v.y + v.z + v.w;
    if (t == 0) sum += extra;
#pragma unroll
    for (int off = 16; off > 0; off >>= 1)
        sum += __shfl_xor_sync(0xffffffffu, sum, off);
    if ((t & 31) == 0) red[t >> 5] = sum;
    __syncthreads();
    float tot = 0.f;
#pragma unroll
    for (int w = 0; w < 8; w++) tot += red[w];
    float inv = 1.0f / tot;
    float* o = out + 1 + (size_t)i * OUT_LD + 4 * t;
    o[0] = v.x * inv;
    o[1] = v.y * inv;
    o[2] = v.z * inv;
    o[3] = v.w * inv;
    if (t == 0) out[1 + (size_t)i * OUT_LD + 1024] = extra * inv;

    // ticket: last block computes the loss from k2's per-block partials
    if (t == 0) {
        __threadfence();
        amLast = (atomicAdd(&g_done, 1u) == NROW - 1);
    }
    __syncthreads();
    if (amLast) {
        float s = g_blockloss[t] + g_blockloss[t + 256];
        if (t < NTILE - 512) s += g_blockloss[t + 512];
#pragma unroll
        for (int off = 16; off > 0; off >>= 1)
            s += __shfl_xor_sync(0xffffffffu, s, off);
        if ((t & 31) == 0) red[t >> 5] = s;
        __syncthreads();
        if (t == 0) {
            float tl = 0.f;
#pragma unroll
            for (int w = 0; w < 8; w++) tl += red[w];
            out[0] = tl * (1.0f / (1024.0f * 1025.0f));
            g_done = 0;   // replay-safe reset
        }
    }
}

extern "C" void kernel_launch(void* const* d_in, const int* in_sizes, int n_in,
                              void* d_out, int out_size) {
    const float* sentence;
    const int*   tgt;
    const float* W1;
    const float* b1;
    const float* W2;
    const float* b2;

    if (n_in >= 6 && in_sizes[1] == 1024) {
        sentence = (const float*)d_in[0];
        tgt      = (const int*)d_in[1];
        W1       = (const float*)d_in[2];
        b1       = (const float*)d_in[3];
        W2       = (const float*)d_in[4];
        b2       = (const float*)d_in[5];
    } else {
        sentence = (const float*)d_in[0];
        W1       = (const float*)d_in[1];
        b1       = (const float*)d_in[2];
        W2       = (const float*)d_in[3];
        b2       = (const float*)d_in[4];
        tgt      = (const int*)d_in[5];
    }

    float* out = (float*)d_out;

    k1_gemm<<<129, 256>>>(sentence, W1, b1, W2, b2);
    dim3 g2(17, 32);
    k2_scores<<<g2, 256>>>(tgt);
    k3_softmax<<<1024, 256>>>(out);
}